// round 17
// baseline (speedup 1.0000x reference)
#include <cuda_runtime.h>
#include <cstdint>

#define MAXG 1024
#define RESI 256
#define GSPLIT 32
#define GCHUNK 32    // MAXG / GSPLIT
#define NTILE 256    // 16x16 tiles

__device__ float4   d_g0[MAXG];                        // mx, my, cA, cB
__device__ float4   d_g1[MAXG];                        // cC, opacity, mask(punned), f=ex2(2cA)
__device__ float    d_partial[GSPLIT * RESI * RESI];   // 8 MB scratch
__device__ unsigned d_count[NTILE];                    // zero-init; +GSPLIT per call per tile

__device__ __forceinline__ float ex2f(float x) {
    float y;
    asm("ex2.approx.ftz.f32 %0, %1;" : "=f"(y) : "f"(x));
    return y;
}

// ---------------------------------------------------------------------------
// Prep: one thread per gaussian -> conic coeffs + tile bits + ratio constant.
// ---------------------------------------------------------------------------
__global__ void prep_kernel(const float* __restrict__ xyz,
                            const float* __restrict__ scaling,
                            const float* __restrict__ rotation,
                            const float* __restrict__ opacity,
                            const float* __restrict__ rot,
                            int N) {
    int i = blockIdx.x * blockDim.x + threadIdx.x;
    if (i >= N) return;
    const float RES = (float)RESI;

    float qr = rotation[4 * i + 0];
    float qx = rotation[4 * i + 1];
    float qy = rotation[4 * i + 2];
    float qz = rotation[4 * i + 3];
    float inv = rsqrtf(qr * qr + qx * qx + qy * qy + qz * qz);
    qr *= inv; qx *= inv; qy *= inv; qz *= inv;

    float R00 = 1.f - 2.f * (qy * qy + qz * qz);
    float R01 = 2.f * (qx * qy - qr * qz);
    float R02 = 2.f * (qx * qz + qr * qy);
    float R10 = 2.f * (qx * qy + qr * qz);
    float R11 = 1.f - 2.f * (qx * qx + qz * qz);
    float R12 = 2.f * (qy * qz - qr * qx);
    float R20 = 2.f * (qx * qz - qr * qy);
    float R21 = 2.f * (qy * qz + qr * qx);
    float R22 = 1.f - 2.f * (qx * qx + qy * qy);

    float sc0 = scaling[3 * i + 0];
    float sc1 = scaling[3 * i + 1];
    float sc2 = scaling[3 * i + 2];

    float L00 = R00 * sc0, L01 = R01 * sc1, L02 = R02 * sc2;
    float L10 = R10 * sc0, L11 = R11 * sc1, L12 = R12 * sc2;
    float L20 = R20 * sc0, L21 = R21 * sc1, L22 = R22 * sc2;

    float C00 = L00 * L00 + L01 * L01 + L02 * L02;
    float C01 = L00 * L10 + L01 * L11 + L02 * L12;
    float C02 = L00 * L20 + L01 * L21 + L02 * L22;
    float C11 = L10 * L10 + L11 * L11 + L12 * L12;
    float C12 = L10 * L20 + L11 * L21 + L12 * L22;
    float C22 = L20 * L20 + L21 * L21 + L22 * L22;

    float a00 = RES * rot[0], a01 = RES * rot[1], a02 = RES * rot[2];
    float a10 = RES * rot[3], a11 = RES * rot[4], a12 = RES * rot[5];

    float v0x = C00 * a00 + C01 * a01 + C02 * a02;
    float v0y = C01 * a00 + C11 * a01 + C12 * a02;
    float v0z = C02 * a00 + C12 * a01 + C22 * a02;
    float c00 = a00 * v0x + a01 * v0y + a02 * v0z;
    float c01 = a10 * v0x + a11 * v0y + a12 * v0z;
    float v1x = C00 * a10 + C01 * a11 + C02 * a12;
    float v1y = C01 * a10 + C11 * a11 + C12 * a12;
    float v1z = C02 * a10 + C12 * a11 + C22 * a12;
    float c11 = a10 * v1x + a11 * v1y + a12 * v1z;

    float det = c00 * c11 - c01 * c01;
    float mid = 0.5f * (c00 + c11);
    float sq = sqrtf(fmaxf(mid * mid - det, 0.1f));
    float lam = fmaxf(mid + sq, mid - sq);
    float radii = ceilf(3.0f * sqrtf(lam));

    float mx = xyz[3 * i + 0] * (RES * 0.5f);
    float my = xyz[3 * i + 1] * (RES * 0.5f);

    float rminx = fminf(fmaxf(mx - radii, 0.f), RES - 1.f);
    float rmaxx = fminf(fmaxf(mx + radii, 0.f), RES - 1.f);
    float rminy = fminf(fmaxf(my - radii, 0.f), RES - 1.f);
    float rmaxy = fminf(fmaxf(my + radii, 0.f), RES - 1.f);

    unsigned mw = 0u;
    #pragma unroll
    for (int tt = 0; tt < 16; tt++) {
        float ts = (float)(tt * 16);
        if (fminf(rmaxx, ts + 15.f) > fmaxf(rminx, ts)) mw |= (1u << tt);
        if (fminf(rmaxy, ts + 15.f) > fmaxf(rminy, ts)) mw |= (1u << (16 + tt));
    }

    float idet = 1.0f / det;
    const float L2E = 1.4426950408889634f;
    float cA = -0.5f * L2E * (c11 * idet);
    float cB = -0.5f * L2E * (c00 * idet);
    float cC = -0.5f * L2E * (-2.0f * c01 * idet);
    float f  = ex2f(2.0f * cA);      // constant second-difference ratio (<=1)

    d_g0[i] = make_float4(mx, my, cA, cB);
    d_g1[i] = make_float4(cC, opacity[i], __uint_as_float(mw), f);
}

// ---------------------------------------------------------------------------
// Splat: one CTA = ONE WARP = one 16x16 tile x one 32-gaussian chunk.
// Thread t owns 8 px of row t>>1 (half = t&1). Geometric-ratio chain:
// 2 EX2 + 13 FMUL + 8 FFMA per 8 pixels; setup amortized over 8 px.
// ---------------------------------------------------------------------------
__global__ void __launch_bounds__(32) splat_kernel(float* __restrict__ out, int N) {
    __shared__ float4 c0[GCHUNK];         // mx, my, cA, cB (compacted)
    __shared__ float4 c1[GCHUNK];         // cC, opacity, f, 0 (compacted)

    int bid = blockIdx.x;
    int s   = bid & (GSPLIT - 1);   // gaussian split 0..31
    int blk = bid >> 5;             // tile 0..255
    int bx  = blk & 15;             // tile column
    int ty  = blk >> 4;             // tile row

    int g0 = s * GCHUNK;
    int gN = N - g0;
    if (gN > GCHUNK) gN = GCHUNK;
    if (gN < 0) gN = 0;

    int t = threadIdx.x;            // 0..31 (one warp)

    // ---- Phase 1: single-round load + mask test + compact ----
    float4 q0a, q1a;
    bool pa = false;
    if (t < gN) {
        q0a = d_g0[g0 + t];
        q1a = d_g1[g0 + t];
        unsigned mw = __float_as_uint(q1a.z);
        pa = ((mw >> bx) & (mw >> (16 + ty)) & 1u) != 0u;
    }
    unsigned bal = __ballot_sync(0xffffffffu, pa);
    int cnt = __popc(bal);
    if (pa) {
        int p = __popc(bal & ((1u << t) - 1u));
        c0[p] = q0a;
        c1[p] = make_float4(q1a.x, q1a.y, q1a.w, 0.f);
    }
    __syncwarp();

    // ---- Phase 2: dense splat, 8 px per thread (half of one row) ----
    int row  = t >> 1;              // 0..15
    int half = t & 1;               // 0 or 1
    int x = bx * 16 + half * 8;
    int y = ty * 16 + row;

    float px = (float)x - 127.5f;
    float py = (float)y - 127.5f;

    float a0 = 0.f, a1 = 0.f, a2 = 0.f, a3 = 0.f;
    float a4 = 0.f, a5 = 0.f, a6 = 0.f, a7 = 0.f;

    #pragma unroll 2
    for (int i = 0; i < cnt; i++) {
        float4 q0 = c0[i];
        float4 q1 = c1[i];
        float dx = px - q0.x;
        float dy = py - q0.y;
        float cAi = q0.z;
        float h  = q1.x * dy;               // cC * dy
        float sB = q0.w * (dy * dy);        // cB * dy^2
        float o  = q1.y;
        float f  = q1.z;                    // ex2(2*cA), <= 1

        float inner = fmaf(cAi, dx, h);     // cA*dx + h
        float g     = fmaf(cAi, dx, inner); // 2*cA*dx + h
        float base  = fmaf(dx, inner, sB);  // q(0)

        float w0 = ex2f(base);
        float r  = fminf(ex2f(g + cAi), 1e30f);  // ratio w1/w0; clamp kills 0*inf
        float w1 = w0 * r;  r *= f;
        float w2 = w1 * r;  r *= f;
        float w3 = w2 * r;  r *= f;
        float w4 = w3 * r;  r *= f;
        float w5 = w4 * r;  r *= f;
        float w6 = w5 * r;  r *= f;
        float w7 = w6 * r;

        a0 = fmaf(w0, o, a0);
        a1 = fmaf(w1, o, a1);
        a2 = fmaf(w2, o, a2);
        a3 = fmaf(w3, o, a3);
        a4 = fmaf(w4, o, a4);
        a5 = fmaf(w5, o, a5);
        a6 = fmaf(w6, o, a6);
        a7 = fmaf(w7, o, a7);
    }

    int pix = y * RESI + x;
    float4* pp = reinterpret_cast<float4*>(&d_partial[s * (RESI * RESI) + pix]);
    pp[0] = make_float4(a0, a1, a2, a3);
    pp[1] = make_float4(a4, a5, a6, a7);

    // ---- Phase 3: last-CTA-per-tile reduction (deterministic order) ----
    __threadfence();
    unsigned old = 0u;
    if (t == 0) old = atomicAdd(&d_count[blk], 1u);
    old = __shfl_sync(0xffffffffu, old, 0);

    if (((old + 1) & (GSPLIT - 1)) == 0) {
        const float4* p = reinterpret_cast<const float4*>(d_partial);
        int idx = pix >> 2;                     // my first float4
        float4 r0 = __ldcg(&p[idx]);
        float4 r1 = __ldcg(&p[idx + 1]);
        #pragma unroll 8
        for (int ss = 1; ss < GSPLIT; ss++) {
            const float4* q = &p[ss * (RESI * RESI / 4)];
            float4 b0 = __ldcg(&q[idx]);
            float4 b1 = __ldcg(&q[idx + 1]);
            r0.x += b0.x; r0.y += b0.y; r0.z += b0.z; r0.w += b0.w;
            r1.x += b1.x; r1.y += b1.y; r1.z += b1.z; r1.w += b1.w;
        }
        float4* po = reinterpret_cast<float4*>(&out[pix]);
        po[0] = r0;
        po[1] = r1;
    }
}

// ---------------------------------------------------------------------------
extern "C" void kernel_launch(void* const* d_in, const int* in_sizes, int n_in,
                              void* d_out, int out_size) {
    const float* xyz      = (const float*)d_in[0];
    const float* scaling  = (const float*)d_in[1];
    const float* rotation = (const float*)d_in[2];
    const float* opacity  = (const float*)d_in[3];
    const float* rot      = (const float*)d_in[4];

    int N = in_sizes[0] / 3;
    if (N > MAXG) N = MAXG;

    prep_kernel<<<(N + 127) / 128, 128>>>(xyz, scaling, rotation, opacity, rot, N);
    splat_kernel<<<NTILE * GSPLIT, 32>>>((float*)d_out, N);
}